// round 5
// baseline (speedup 1.0000x reference)
#include <cuda_runtime.h>
#include <math.h>

// YOLO loss: preds/targets [N,7,7,30] fp32 -> scalar fp32.
// Single-kernel streaming reduction; last block (fence+ticket) finalizes.

constexpr int D   = 30;    // floats per cell
constexpr int BLK = 128;   // threads per block == cells per block
constexpr float LAMBDA_NOOBJ = 0.5f;
constexpr float EPS_IOU      = 1e-10f;

constexpr int MAX_BLOCKS = 16384;
__device__ float        g_part[MAX_BLOCKS];
__device__ unsigned int g_ticket = 0;

__global__ void __launch_bounds__(BLK)
yolo_fused_kernel(const float* __restrict__ preds,
                  const float* __restrict__ targets,
                  float* __restrict__ out,
                  int n_cells, int N)
{
    __shared__ float sp[BLK * D];
    __shared__ float st[BLK * D];
    __shared__ float warp_sums[BLK / 32];
    __shared__ bool  is_last;

    const int tid   = threadIdx.x;
    const int cell0 = blockIdx.x * BLK;

    float loss = 0.0f;   // class loss fused into the streaming pass

    // ---- Stage 1: coalesced global -> smem (identity layout), fused class loss ----
    if (cell0 + BLK <= n_cells) {
        const float4* p4 = reinterpret_cast<const float4*>(preds   + (size_t)cell0 * D);
        const float4* t4 = reinterpret_cast<const float4*>(targets + (size_t)cell0 * D);
        float4* sp4 = reinterpret_cast<float4*>(sp);
        float4* st4 = reinterpret_cast<float4*>(st);
        constexpr int NV = BLK * D / 4;          // 960 float4 per array
        #pragma unroll
        for (int it = 0; it < (NV + BLK - 1) / BLK; ++it) {
            int i = tid + it * BLK;
            if (i < NV) {
                float4 vp = p4[i];
                float4 vt = t4[i];
                sp4[i] = vp;
                st4[i] = vt;
                // class channels are j >= 10 where j = (4i+k) mod 30
                int f = i * 4;
                int c = f / D;
                int j = f - c * D;               // even, 0..28
                float d;
                d = vp.x - vt.x; if (j     >= 10) loss += d * d;
                d = vp.y - vt.y; if (j + 1 >= 10) loss += d * d;   // j+1 <= 29, no wrap
                int j2 = (j + 2 >= D) ? j + 2 - D : j + 2;
                int j3 = (j + 3 >= D) ? j + 3 - D : j + 3;
                d = vp.z - vt.z; if (j2    >= 10) loss += d * d;
                d = vp.w - vt.w; if (j3    >= 10) loss += d * d;
            }
        }
    } else {
        // Tail block: guarded scalar path (same fused class loss).
        int lim = (n_cells - cell0) * D;
        for (int f = tid; f < BLK * D; f += BLK) {
            int c = f / D;
            int j = f - c * D;
            float vp = 0.f, vt = 0.f;
            if (f < lim) {
                vp = preds  [(size_t)cell0 * D + f];
                vt = targets[(size_t)cell0 * D + f];
            }
            sp[f] = vp;
            st[f] = vt;
            if (j >= 10) { float d = vp - vt; loss += d * d; }
        }
    }
    __syncthreads();

    // ---- Stage 2: per-cell box/conf terms (one thread per cell) ----
    if (cell0 + tid < n_cells) {
        const float* p = sp + tid * D;
        const float* t = st + tid * D;

        float iou[2];
        #pragma unroll
        for (int b = 0; b < 2; ++b) {
            float px = p[5*b + 0], py = p[5*b + 1], pw = p[5*b + 2], ph = p[5*b + 3];
            float tx = t[5*b + 0], ty = t[5*b + 1], tw = t[5*b + 2], th = t[5*b + 3];
            float iw = fminf(px + 0.5f*pw, tx + 0.5f*tw) - fmaxf(px - 0.5f*pw, tx - 0.5f*tw);
            float ih = fminf(py + 0.5f*ph, ty + 0.5f*th) - fmaxf(py - 0.5f*ph, ty - 0.5f*th);
            iw = fmaxf(0.0f, iw);
            ih = fmaxf(0.0f, ih);
            float inter = iw * ih;
            float uni   = pw * ph + tw * th - inter;
            iou[b] = inter / (uni + EPS_IOU);
        }

        int sel = (iou[1] > iou[0]) ? 1 : 0;        // first max on ties

        bool has_obj = (t[4] > 0.0f);
        float dx = p[5*sel + 0] - t[5*sel + 0];
        float dy = p[5*sel + 1] - t[5*sel + 1];
        if (has_obj) loss += dx*dx + dy*dy;

        // target-class argmax (first max on ties)
        float best = t[10];
        int   gt   = 10;
        #pragma unroll
        for (int c = 1; c < 20; ++c) {
            float tc = t[10 + c];
            if (tc > best) { best = tc; gt = 10 + c; }
        }
        float pcgt = p[gt];

        // conf loss: w * (iou*pcgt - iou)^2 = w * iou^2 * (pcgt-1)^2
        float g = pcgt - 1.0f;
        #pragma unroll
        for (int b = 0; b < 2; ++b) {
            float w    = (b == sel) ? 1.0f : LAMBDA_NOOBJ;
            float diff = iou[b] * g;
            loss += w * diff * diff;
        }
    }

    // ---- Stage 3: block reduce -> partial, ticket, last block finalizes ----
    #pragma unroll
    for (int off = 16; off > 0; off >>= 1)
        loss += __shfl_xor_sync(0xFFFFFFFFu, loss, off);
    if ((tid & 31) == 0) warp_sums[tid >> 5] = loss;
    __syncthreads();
    if (tid == 0) {
        float s = 0.0f;
        #pragma unroll
        for (int w = 0; w < BLK / 32; ++w) s += warp_sums[w];
        g_part[blockIdx.x] = s;
        __threadfence();
        unsigned int t = atomicAdd(&g_ticket, 1u);
        is_last = (t == gridDim.x - 1);
    }
    __syncthreads();

    if (is_last) {
        // All partials are globally visible (fence + full ticket count).
        int nblocks = gridDim.x;
        double s = 0.0;
        for (int i = tid; i < nblocks; i += BLK)
            s += (double)g_part[i];

        #pragma unroll
        for (int off = 16; off > 0; off >>= 1)
            s += __shfl_xor_sync(0xFFFFFFFFu, s, off);

        __shared__ double ws[BLK / 32];
        if ((tid & 31) == 0) ws[tid >> 5] = s;
        __syncthreads();
        if (tid == 0) {
            double tot = 0.0;
            #pragma unroll
            for (int w = 0; w < BLK / 32; ++w) tot += ws[w];
            out[0] = (float)(tot / (double)N);
            g_ticket = 0;   // reset for next graph replay (deterministic)
        }
    }
}

extern "C" void kernel_launch(void* const* d_in, const int* in_sizes, int n_in,
                              void* d_out, int out_size)
{
    const float* preds   = (const float*)d_in[0];
    const float* targets = (const float*)d_in[1];
    float* out = (float*)d_out;

    int total   = in_sizes[0];          // N*7*7*30
    int n_cells = total / D;            // N*49
    int N       = total / (7 * 7 * D);  // batch

    int grid = (n_cells + BLK - 1) / BLK;   // 6272 for this shape
    if (grid > MAX_BLOCKS) grid = MAX_BLOCKS;

    yolo_fused_kernel<<<grid, BLK>>>(preds, targets, out, n_cells, N);
}

// round 10
// speedup vs baseline: 1.0058x; 1.0058x over previous
#include <cuda_runtime.h>
#include <math.h>

// YOLO loss: preds/targets [N,7,7,30] fp32 -> scalar fp32.
// Single-kernel streaming reduction; last block (fence+ticket) finalizes.
// Occupancy-optimized: smem 160B/thread (t full + p boxes), regs capped.

constexpr int D   = 30;    // floats per cell
constexpr int BLK = 128;   // threads per block == cells per block
constexpr float LAMBDA_NOOBJ = 0.5f;
constexpr float EPS_IOU      = 1e-10f;

constexpr int MAX_BLOCKS = 16384;
__device__ float        g_part[MAX_BLOCKS];
__device__ unsigned int g_ticket = 0;

__global__ void __launch_bounds__(BLK, 10)
yolo_fused_kernel(const float* __restrict__ preds,
                  const float* __restrict__ targets,
                  float* __restrict__ out,
                  int n_cells, int N)
{
    __shared__ float st [BLK * D];    // targets: full 30 ch/cell (identity layout)
    __shared__ float spb[BLK * 10];   // preds:   box channels 0..9 only
    __shared__ float warp_sums[BLK / 32];
    __shared__ bool  is_last;

    const int tid   = threadIdx.x;
    const int cell0 = blockIdx.x * BLK;

    float loss = 0.0f;   // class loss fused into the streaming pass

    // ---- Stage 1: coalesced global loads; st identity STS.128, p-boxes scalar ----
    if (cell0 + BLK <= n_cells) {
        const float4* p4 = reinterpret_cast<const float4*>(preds   + (size_t)cell0 * D);
        const float4* t4 = reinterpret_cast<const float4*>(targets + (size_t)cell0 * D);
        float4* st4 = reinterpret_cast<float4*>(st);
        constexpr int NV = BLK * D / 4;          // 960 float4 per array
        #pragma unroll
        for (int it = 0; it < (NV + BLK - 1) / BLK; ++it) {
            int i = tid + it * BLK;
            if (i < NV) {
                float4 vp = p4[i];
                float4 vt = t4[i];
                st4[i] = vt;
                // channel j = (4i+k) mod 30; class iff j >= 10
                int f = i * 4;
                int c = f / D;
                int j = f - c * D;               // even, 0..28
                float d;
                d = vp.x - vt.x;
                if (j >= 10) loss += d * d; else spb[c * 10 + j] = vp.x;
                d = vp.y - vt.y;                  // j+1 <= 29, no wrap
                if (j + 1 >= 10) loss += d * d; else spb[c * 10 + j + 1] = vp.y;
                int c2 = c, j2 = j + 2;
                if (j2 >= D) { j2 -= D; ++c2; }
                d = vp.z - vt.z;
                if (j2 >= 10) loss += d * d; else spb[c2 * 10 + j2] = vp.z;
                int c3 = c, j3 = j + 3;
                if (j3 >= D) { j3 -= D; ++c3; }
                d = vp.w - vt.w;
                if (j3 >= 10) loss += d * d; else spb[c3 * 10 + j3] = vp.w;
            }
        }
    } else {
        // Tail block: guarded scalar path.
        int lim = (n_cells - cell0) * D;
        for (int f = tid; f < BLK * D; f += BLK) {
            int c = f / D;
            int j = f - c * D;
            float vp = 0.f, vt = 0.f;
            if (f < lim) {
                vp = preds  [(size_t)cell0 * D + f];
                vt = targets[(size_t)cell0 * D + f];
            }
            st[f] = vt;
            if (j >= 10) { float d = vp - vt; loss += d * d; }
            else         { spb[c * 10 + j] = vp; }
        }
    }
    __syncthreads();

    // ---- Stage 2: per-cell box/conf terms (one thread per cell) ----
    if (cell0 + tid < n_cells) {
        const float* t = st  + tid * D;
        const float* p = spb + tid * 10;

        float iou[2];
        #pragma unroll
        for (int b = 0; b < 2; ++b) {
            float px = p[5*b + 0], py = p[5*b + 1], pw = p[5*b + 2], ph = p[5*b + 3];
            float tx = t[5*b + 0], ty = t[5*b + 1], tw = t[5*b + 2], th = t[5*b + 3];
            float iw = fminf(px + 0.5f*pw, tx + 0.5f*tw) - fmaxf(px - 0.5f*pw, tx - 0.5f*tw);
            float ih = fminf(py + 0.5f*ph, ty + 0.5f*th) - fmaxf(py - 0.5f*ph, ty - 0.5f*th);
            iw = fmaxf(0.0f, iw);
            ih = fmaxf(0.0f, ih);
            float inter = iw * ih;
            float uni   = pw * ph + tw * th - inter;
            iou[b] = inter / (uni + EPS_IOU);
        }

        int sel = (iou[1] > iou[0]) ? 1 : 0;        // first max on ties

        bool has_obj = (t[4] > 0.0f);
        float dx = p[5*sel + 0] - t[5*sel + 0];
        float dy = p[5*sel + 1] - t[5*sel + 1];
        if (has_obj) loss += dx*dx + dy*dy;

        // target-class argmax (first max on ties)
        float best = t[10];
        int   gt   = 0;
        #pragma unroll
        for (int c = 1; c < 20; ++c) {
            float tc = t[10 + c];
            if (tc > best) { best = tc; gt = c; }
        }
        // pcgt: single scattered global read (L1/L2-warm from stage 1)
        float pcgt = __ldg(&preds[(size_t)(cell0 + tid) * D + 10 + gt]);

        // conf loss: w * (iou*pcgt - iou)^2 = w * iou^2 * (pcgt-1)^2
        float g = pcgt - 1.0f;
        #pragma unroll
        for (int b = 0; b < 2; ++b) {
            float w    = (b == sel) ? 1.0f : LAMBDA_NOOBJ;
            float diff = iou[b] * g;
            loss += w * diff * diff;
        }
    }

    // ---- Stage 3: block reduce -> partial, ticket, last block finalizes ----
    #pragma unroll
    for (int off = 16; off > 0; off >>= 1)
        loss += __shfl_xor_sync(0xFFFFFFFFu, loss, off);
    if ((tid & 31) == 0) warp_sums[tid >> 5] = loss;
    __syncthreads();
    if (tid == 0) {
        float s = 0.0f;
        #pragma unroll
        for (int w = 0; w < BLK / 32; ++w) s += warp_sums[w];
        g_part[blockIdx.x] = s;
        __threadfence();
        unsigned int tk = atomicAdd(&g_ticket, 1u);
        is_last = (tk == gridDim.x - 1);
    }
    __syncthreads();

    if (is_last) {
        int nblocks = gridDim.x;
        double s = 0.0;
        for (int i = tid; i < nblocks; i += BLK)
            s += (double)g_part[i];

        #pragma unroll
        for (int off = 16; off > 0; off >>= 1)
            s += __shfl_xor_sync(0xFFFFFFFFu, s, off);

        __shared__ double ws[BLK / 32];
        if ((tid & 31) == 0) ws[tid >> 5] = s;
        __syncthreads();
        if (tid == 0) {
            double tot = 0.0;
            #pragma unroll
            for (int w = 0; w < BLK / 32; ++w) tot += ws[w];
            out[0] = (float)(tot / (double)N);
            g_ticket = 0;   // reset for next graph replay (deterministic)
        }
    }
}

extern "C" void kernel_launch(void* const* d_in, const int* in_sizes, int n_in,
                              void* d_out, int out_size)
{
    const float* preds   = (const float*)d_in[0];
    const float* targets = (const float*)d_in[1];
    float* out = (float*)d_out;

    int total   = in_sizes[0];          // N*7*7*30
    int n_cells = total / D;            // N*49
    int N       = total / (7 * 7 * D);  // batch

    int grid = (n_cells + BLK - 1) / BLK;   // 6272 for this shape
    if (grid > MAX_BLOCKS) grid = MAX_BLOCKS;

    yolo_fused_kernel<<<grid, BLK>>>(preds, targets, out, n_cells, N);
}

// round 11
// speedup vs baseline: 1.3333x; 1.3257x over previous
#include <cuda_runtime.h>
#include <math.h>
#include <stdint.h>

// YOLO loss: preds/targets [N,7,7,30] fp32 -> scalar fp32.
// Persistent blocks + double-buffered cp.async pipeline (register-free MLP),
// single launch, fence+ticket finalize.

constexpr int D    = 30;                 // floats per cell
constexpr int BLK  = 128;                // threads per block == cells per tile
constexpr int TILE_FLOATS = BLK * D;     // 3840 floats per array per tile
constexpr int TILE_VEC    = TILE_FLOATS / 4;   // 960 float4
constexpr int SMEM_BYTES  = 2 * 2 * TILE_FLOATS * 4;  // stages x {p,t} = 61440 B
constexpr float LAMBDA_NOOBJ = 0.5f;
constexpr float EPS_IOU      = 1e-10f;

constexpr int GRID = 444;                // 148 SMs x 3 blocks (smem-bound)
__device__ float        g_part[GRID];
__device__ unsigned int g_ticket = 0;

__device__ __forceinline__ void cp_async16(uint32_t dst_smem, const void* src) {
    asm volatile("cp.async.cg.shared.global [%0], [%1], 16;\n"
                 :: "r"(dst_smem), "l"(src));
}
__device__ __forceinline__ void cp_commit() {
    asm volatile("cp.async.commit_group;\n");
}
__device__ __forceinline__ void cp_wait1() {
    asm volatile("cp.async.wait_group 1;\n");
}

__global__ void __launch_bounds__(BLK)
yolo_fused_kernel(const float* __restrict__ preds,
                  const float* __restrict__ targets,
                  float* __restrict__ out,
                  int n_cells, int N, int n_tiles)
{
    extern __shared__ float buf[];   // [stage][2][TILE_FLOATS]
    __shared__ float warp_sums[BLK / 32];
    __shared__ bool  is_last;

    const int tid = threadIdx.x;
    const uint32_t buf_s32 = (uint32_t)__cvta_generic_to_shared(buf);

    float loss = 0.0f;

    // ---- tile loader: async for full tiles, sync-guarded for the (rare) tail ----
    auto load_tile = [&](int tile, int stage) {
        const size_t base = (size_t)tile * TILE_FLOATS;
        float* sp = buf + stage * 2 * TILE_FLOATS;
        float* st = sp + TILE_FLOATS;
        if ((tile + 1) * BLK <= n_cells) {
            const float4* p4 = reinterpret_cast<const float4*>(preds   + base);
            const float4* t4 = reinterpret_cast<const float4*>(targets + base);
            uint32_t sp32 = buf_s32 + (uint32_t)(stage * 2 * TILE_FLOATS) * 4u;
            uint32_t st32 = sp32 + TILE_FLOATS * 4u;
            #pragma unroll
            for (int k = 0; k < (TILE_VEC + BLK - 1) / BLK; ++k) {
                int i = tid + k * BLK;
                if (i < TILE_VEC) {
                    cp_async16(sp32 + i * 16u, p4 + i);
                    cp_async16(st32 + i * 16u, t4 + i);
                }
            }
        } else {
            // tail tile: synchronous guarded fill (visible after __syncthreads)
            int lim = (n_cells - tile * BLK) * D;
            for (int f = tid; f < TILE_FLOATS; f += BLK) {
                float vp = 0.f, vt = 0.f;
                if (f < lim) {
                    vp = preds  [base + f];
                    vt = targets[base + f];
                }
                sp[f] = vp;
                st[f] = vt;
            }
        }
    };

    // ---- per-tile compute: one thread per cell, all data pulled into regs ----
    auto compute_tile = [&](int tile, int stage) {
        int cell = tile * BLK + tid;
        if (cell >= n_cells) return;
        const float* sp = buf + stage * 2 * TILE_FLOATS;
        const float* st = sp + TILE_FLOATS;
        const float2* p2 = reinterpret_cast<const float2*>(sp + tid * D);
        const float2* t2 = reinterpret_cast<const float2*>(st + tid * D);

        float p[D], t[D];
        #pragma unroll
        for (int i = 0; i < D / 2; ++i) {
            float2 a = p2[i]; p[2*i] = a.x; p[2*i+1] = a.y;
            float2 b = t2[i]; t[2*i] = b.x; t[2*i+1] = b.y;
        }

        // IoU for the 2 paired boxes
        float iou[2];
        #pragma unroll
        for (int b = 0; b < 2; ++b) {
            float px = p[5*b+0], py = p[5*b+1], pw = p[5*b+2], ph = p[5*b+3];
            float tx = t[5*b+0], ty = t[5*b+1], tw = t[5*b+2], th = t[5*b+3];
            float iw = fminf(px + 0.5f*pw, tx + 0.5f*tw) - fmaxf(px - 0.5f*pw, tx - 0.5f*tw);
            float ih = fminf(py + 0.5f*ph, ty + 0.5f*th) - fmaxf(py - 0.5f*ph, ty - 0.5f*th);
            iw = fmaxf(0.0f, iw);
            ih = fmaxf(0.0f, ih);
            float inter = iw * ih;
            float uni   = pw * ph + tw * th - inter;
            iou[b] = inter / (uni + EPS_IOU);
        }

        int sel = (iou[1] > iou[0]) ? 1 : 0;          // first max on ties

        // coord loss, masked by has_obj = targets[...,4] > 0
        if (t[4] > 0.0f) {
            float dx = (sel ? p[5] : p[0]) - (sel ? t[5] : t[0]);
            float dy = (sel ? p[6] : p[1]) - (sel ? t[6] : t[1]);
            loss += dx*dx + dy*dy;
        }

        // class loss + target-class argmax with pcgt tracked in-loop (no var-index)
        float best = t[10], pcgt = p[10];
        #pragma unroll
        for (int c = 0; c < 20; ++c) {
            float d = p[10 + c] - t[10 + c];
            loss += d * d;
        }
        #pragma unroll
        for (int c = 1; c < 20; ++c) {
            float tc = t[10 + c];
            if (tc > best) { best = tc; pcgt = p[10 + c]; }
        }

        // conf loss: w * (iou*pcgt - iou)^2 = w * iou^2 * (pcgt-1)^2
        float g = pcgt - 1.0f;
        #pragma unroll
        for (int b = 0; b < 2; ++b) {
            float w    = (b == sel) ? 1.0f : LAMBDA_NOOBJ;
            float diff = iou[b] * g;
            loss += w * diff * diff;
        }
    };

    // ---- double-buffered pipeline over this block's strided tiles ----
    int t_cur = blockIdx.x;
    int stage = 0;
    if (t_cur < n_tiles) load_tile(t_cur, 0);
    cp_commit();

    while (t_cur < n_tiles) {
        int t_next = t_cur + gridDim.x;
        if (t_next < n_tiles) load_tile(t_next, stage ^ 1);
        cp_commit();                 // may be an empty group (harmless)
        cp_wait1();                  // current tile's group is complete
        __syncthreads();             // smem visible to all threads
        compute_tile(t_cur, stage);
        __syncthreads();             // all reads done before buffer reuse
        t_cur = t_next;
        stage ^= 1;
    }

    // ---- block reduce -> partial, ticket, last block finalizes ----
    #pragma unroll
    for (int off = 16; off > 0; off >>= 1)
        loss += __shfl_xor_sync(0xFFFFFFFFu, loss, off);
    if ((tid & 31) == 0) warp_sums[tid >> 5] = loss;
    __syncthreads();
    if (tid == 0) {
        float s = 0.0f;
        #pragma unroll
        for (int w = 0; w < BLK / 32; ++w) s += warp_sums[w];
        g_part[blockIdx.x] = s;
        __threadfence();
        unsigned int tk = atomicAdd(&g_ticket, 1u);
        is_last = (tk == gridDim.x - 1);
    }
    __syncthreads();

    if (is_last) {
        int nblocks = gridDim.x;
        double s = 0.0;
        for (int i = tid; i < nblocks; i += BLK)
            s += (double)g_part[i];
        #pragma unroll
        for (int off = 16; off > 0; off >>= 1)
            s += __shfl_xor_sync(0xFFFFFFFFu, s, off);
        __shared__ double ws[BLK / 32];
        if ((tid & 31) == 0) ws[tid >> 5] = s;
        __syncthreads();
        if (tid == 0) {
            double tot = 0.0;
            #pragma unroll
            for (int w = 0; w < BLK / 32; ++w) tot += ws[w];
            out[0] = (float)(tot / (double)N);
            g_ticket = 0;            // reset for next graph replay
        }
    }
}

extern "C" void kernel_launch(void* const* d_in, const int* in_sizes, int n_in,
                              void* d_out, int out_size)
{
    const float* preds   = (const float*)d_in[0];
    const float* targets = (const float*)d_in[1];
    float* out = (float*)d_out;

    int total   = in_sizes[0];          // N*7*7*30
    int n_cells = total / D;            // N*49
    int N       = total / (7 * 7 * D);  // batch
    int n_tiles = (n_cells + BLK - 1) / BLK;   // 6272 for this shape

    cudaFuncSetAttribute(yolo_fused_kernel,
                         cudaFuncAttributeMaxDynamicSharedMemorySize, SMEM_BYTES);

    int grid = (n_tiles < GRID) ? n_tiles : GRID;
    yolo_fused_kernel<<<grid, BLK, SMEM_BYTES>>>(preds, targets, out,
                                                 n_cells, N, n_tiles);
}

// round 13
// speedup vs baseline: 1.4203x; 1.0652x over previous
#include <cuda_runtime.h>
#include <math.h>
#include <stdint.h>

// YOLO loss: preds/targets [N,7,7,30] fp32 -> scalar fp32.
// Persistent blocks + double-buffered cp.async.bulk (TMA 1D) pipeline with
// mbarrier completion; single launch; fence+ticket finalize.

constexpr int D    = 30;                 // floats per cell
constexpr int BLK  = 128;                // threads per block == cells per tile
constexpr int TILE_FLOATS = BLK * D;     // 3840 floats per array per tile
constexpr int TILE_BYTES  = TILE_FLOATS * 4;          // 15360 B
constexpr int SMEM_BYTES  = 2 * 2 * TILE_BYTES;       // stages x {p,t} = 61440 B
constexpr float LAMBDA_NOOBJ = 0.5f;
constexpr float EPS_IOU      = 1e-10f;

constexpr int GRID = 444;                // 148 SMs x 3 blocks (smem-bound)
__device__ float        g_part[GRID];
__device__ unsigned int g_ticket = 0;

__device__ __forceinline__ void mbar_init(uint32_t mbar, uint32_t count) {
    asm volatile("mbarrier.init.shared.b64 [%0], %1;" :: "r"(mbar), "r"(count) : "memory");
}
__device__ __forceinline__ void mbar_expect_tx(uint32_t mbar, uint32_t bytes) {
    asm volatile("mbarrier.arrive.expect_tx.shared.b64 _, [%0], %1;"
                 :: "r"(mbar), "r"(bytes) : "memory");
}
__device__ __forceinline__ void mbar_arrive(uint32_t mbar) {
    asm volatile("mbarrier.arrive.shared.b64 _, [%0];" :: "r"(mbar) : "memory");
}
__device__ __forceinline__ void mbar_wait(uint32_t mbar, uint32_t parity) {
    asm volatile(
        "{\n\t"
        ".reg .pred P;\n\t"
        "W_%=:\n\t"
        "mbarrier.try_wait.parity.acquire.cta.shared::cta.b64 P, [%0], %1, 0x989680;\n\t"
        "@P bra D_%=;\n\t"
        "bra W_%=;\n\t"
        "D_%=:\n\t"
        "}"
        :: "r"(mbar), "r"(parity) : "memory");
}
__device__ __forceinline__ void bulk_copy_g2s(uint32_t dst_smem, const void* src,
                                              uint32_t bytes, uint32_t mbar) {
    asm volatile(
        "cp.async.bulk.shared::cta.global.mbarrier::complete_tx::bytes "
        "[%0], [%1], %2, [%3];"
        :: "r"(dst_smem), "l"(src), "r"(bytes), "r"(mbar) : "memory");
}

__global__ void __launch_bounds__(BLK)
yolo_fused_kernel(const float* __restrict__ preds,
                  const float* __restrict__ targets,
                  float* __restrict__ out,
                  int n_cells, int N, int n_tiles)
{
    extern __shared__ float buf[];           // [stage][{p,t}][TILE_FLOATS]
    __shared__ __align__(8) uint64_t mbars[2];
    __shared__ float warp_sums[BLK / 32];
    __shared__ bool  is_last;

    const int tid = threadIdx.x;
    const uint32_t buf_s32  = (uint32_t)__cvta_generic_to_shared(buf);
    const uint32_t mbar_s32 = (uint32_t)__cvta_generic_to_shared(mbars);

    if (tid == 0) {
        mbar_init(mbar_s32,     1);
        mbar_init(mbar_s32 + 8, 1);
    }
    __syncthreads();

    float loss = 0.0f;
    int   phase[2] = {0, 0};

    // ---- tile loader ----
    auto load_tile = [&](int tile, int stage) {
        const size_t base = (size_t)tile * TILE_FLOATS;
        const uint32_t mb = mbar_s32 + stage * 8;
        if ((tile + 1) * BLK <= n_cells) {
            if (tid == 0) {
                uint32_t sp32 = buf_s32 + (uint32_t)(stage * 2 * TILE_BYTES);
                mbar_expect_tx(mb, 2 * TILE_BYTES);
                bulk_copy_g2s(sp32,              preds   + base, TILE_BYTES, mb);
                bulk_copy_g2s(sp32 + TILE_BYTES, targets + base, TILE_BYTES, mb);
            }
        } else {
            // tail tile: synchronous guarded fill, then plain arrive
            float* sp = buf + stage * 2 * TILE_FLOATS;
            float* st = sp + TILE_FLOATS;
            int lim = (n_cells - tile * BLK) * D;
            for (int f = tid; f < TILE_FLOATS; f += BLK) {
                float vp = 0.f, vt = 0.f;
                if (f < lim) {
                    vp = preds  [base + f];
                    vt = targets[base + f];
                }
                sp[f] = vp;
                st[f] = vt;
            }
            __syncthreads();
            if (tid == 0) mbar_arrive(mb);
        }
    };

    // ---- per-tile compute: one thread per cell, all data pulled into regs ----
    auto compute_tile = [&](int tile, int stage) {
        int cell = tile * BLK + tid;
        if (cell >= n_cells) return;
        const float* sp = buf + stage * 2 * TILE_FLOATS;
        const float* st = sp + TILE_FLOATS;
        const float2* p2 = reinterpret_cast<const float2*>(sp + tid * D);
        const float2* t2 = reinterpret_cast<const float2*>(st + tid * D);

        float p[D], t[D];
        #pragma unroll
        for (int i = 0; i < D / 2; ++i) {
            float2 a = p2[i]; p[2*i] = a.x; p[2*i+1] = a.y;
            float2 b = t2[i]; t[2*i] = b.x; t[2*i+1] = b.y;
        }

        float iou[2];
        #pragma unroll
        for (int b = 0; b < 2; ++b) {
            float px = p[5*b+0], py = p[5*b+1], pw = p[5*b+2], ph = p[5*b+3];
            float tx = t[5*b+0], ty = t[5*b+1], tw = t[5*b+2], th = t[5*b+3];
            float iw = fminf(px + 0.5f*pw, tx + 0.5f*tw) - fmaxf(px - 0.5f*pw, tx - 0.5f*tw);
            float ih = fminf(py + 0.5f*ph, ty + 0.5f*th) - fmaxf(py - 0.5f*ph, ty - 0.5f*th);
            iw = fmaxf(0.0f, iw);
            ih = fmaxf(0.0f, ih);
            float inter = iw * ih;
            float uni   = pw * ph + tw * th - inter;
            iou[b] = inter / (uni + EPS_IOU);
        }

        int sel = (iou[1] > iou[0]) ? 1 : 0;          // first max on ties

        if (t[4] > 0.0f) {
            float dx = (sel ? p[5] : p[0]) - (sel ? t[5] : t[0]);
            float dy = (sel ? p[6] : p[1]) - (sel ? t[6] : t[1]);
            loss += dx*dx + dy*dy;
        }

        // class loss + target-class argmax with pcgt tracked in-loop
        float best = t[10], pcgt = p[10];
        #pragma unroll
        for (int c = 0; c < 20; ++c) {
            float d = p[10 + c] - t[10 + c];
            loss += d * d;
        }
        #pragma unroll
        for (int c = 1; c < 20; ++c) {
            float tc = t[10 + c];
            if (tc > best) { best = tc; pcgt = p[10 + c]; }
        }

        // conf loss: w * (iou*pcgt - iou)^2 = w * iou^2 * (pcgt-1)^2
        float g = pcgt - 1.0f;
        #pragma unroll
        for (int b = 0; b < 2; ++b) {
            float w    = (b == sel) ? 1.0f : LAMBDA_NOOBJ;
            float diff = iou[b] * g;
            loss += w * diff * diff;
        }
    };

    // ---- double-buffered pipeline over this block's strided tiles ----
    int t_cur = blockIdx.x;
    int stage = 0;
    if (t_cur < n_tiles) load_tile(t_cur, 0);

    while (t_cur < n_tiles) {
        int t_next = t_cur + gridDim.x;
        if (t_next < n_tiles) load_tile(t_next, stage ^ 1);
        mbar_wait(mbar_s32 + stage * 8, phase[stage]);
        phase[stage] ^= 1;
        compute_tile(t_cur, stage);
        __syncthreads();             // all reads done before buffer reuse
        t_cur = t_next;
        stage ^= 1;
    }

    // ---- block reduce -> partial, ticket, last block finalizes ----
    #pragma unroll
    for (int off = 16; off > 0; off >>= 1)
        loss += __shfl_xor_sync(0xFFFFFFFFu, loss, off);
    if ((tid & 31) == 0) warp_sums[tid >> 5] = loss;
    __syncthreads();
    if (tid == 0) {
        float s = 0.0f;
        #pragma unroll
        for (int w = 0; w < BLK / 32; ++w) s += warp_sums[w];
        g_part[blockIdx.x] = s;
        __threadfence();
        unsigned int tk = atomicAdd(&g_ticket, 1u);
        is_last = (tk == gridDim.x - 1);
    }
    __syncthreads();

    if (is_last) {
        int nblocks = gridDim.x;
        double s = 0.0;
        for (int i = tid; i < nblocks; i += BLK)
            s += (double)g_part[i];
        #pragma unroll
        for (int off = 16; off > 0; off >>= 1)
            s += __shfl_xor_sync(0xFFFFFFFFu, s, off);
        __shared__ double ws[BLK / 32];
        if ((tid & 31) == 0) ws[tid >> 5] = s;
        __syncthreads();
        if (tid == 0) {
            double tot = 0.0;
            #pragma unroll
            for (int w = 0; w < BLK / 32; ++w) tot += ws[w];
            out[0] = (float)(tot / (double)N);
            g_ticket = 0;            // reset for next graph replay
        }
    }
}

extern "C" void kernel_launch(void* const* d_in, const int* in_sizes, int n_in,
                              void* d_out, int out_size)
{
    const float* preds   = (const float*)d_in[0];
    const float* targets = (const float*)d_in[1];
    float* out = (float*)d_out;

    int total   = in_sizes[0];          // N*7*7*30
    int n_cells = total / D;            // N*49
    int N       = total / (7 * 7 * D);  // batch
    int n_tiles = (n_cells + BLK - 1) / BLK;   // 6272 for this shape

    cudaFuncSetAttribute(yolo_fused_kernel,
                         cudaFuncAttributeMaxDynamicSharedMemorySize, SMEM_BYTES);

    int grid = (n_tiles < GRID) ? n_tiles : GRID;
    yolo_fused_kernel<<<grid, BLK, SMEM_BYTES>>>(preds, targets, out,
                                                 n_cells, N, n_tiles);
}